// round 9
// baseline (speedup 1.0000x reference)
#include <cuda_runtime.h>
#include <cuda_bf16.h>
#include <cstdint>

// RNN h_t = tanh([x_t,h_{t-1}]@Wc + bc); out = h_T@Wo + bo
// B=4096, T=128, D=128, H=150, O=10.
// mma.sync.m16n8k16 bf16, 3-pass split. R9: 4 warps (128 thr), each warp owns
// m32 x 5 n8-tiles (B-frags loaded ONCE per SM), explicit frag double-buffer.

#define T_SEQ 128
#define D_IN  128
#define H_HID 150
#define O_OUT 10
#define M_BLK 32
#define NPAD  152            // 19 n8-tiles, warp groups (5,5,5,4)
#define KTILES 18
#define ASTR  296
#define ASTRB 592
#define NTHR  128

// SMEM byte offsets
#define SM_AH   0
#define SM_AL   18944                 // +32*592
#define SM_WH   37888                 // +32*592
#define SM_WL   127872                // +152*592
#define SM_BIAS 217856                // +152*592
#define SMEM_BYTES 218464             // +152*4

typedef unsigned int u32;

__device__ __forceinline__ u32 smem_u32(const void* p) {
    u32 a;
    asm("{ .reg .u64 t; cvta.to.shared.u64 t, %1; cvt.u32.u64 %0, t; }" : "=r"(a) : "l"(p));
    return a;
}
__device__ __forceinline__ void ldsm_x4(u32* r, u32 addr) {
    asm volatile("ldmatrix.sync.aligned.m8n8.x4.shared.b16 {%0,%1,%2,%3}, [%4];"
        : "=r"(r[0]), "=r"(r[1]), "=r"(r[2]), "=r"(r[3]) : "r"(addr));
}
__device__ __forceinline__ void ldsm_x2(u32* r, u32 addr) {
    asm volatile("ldmatrix.sync.aligned.m8n8.x2.shared.b16 {%0,%1}, [%2];"
        : "=r"(r[0]), "=r"(r[1]) : "r"(addr));
}
__device__ __forceinline__ void mma16816(float* c, const u32* a, u32 b0, u32 b1) {
    asm volatile("mma.sync.aligned.m16n8k16.row.col.f32.bf16.bf16.f32 "
        "{%0,%1,%2,%3}, {%4,%5,%6,%7}, {%8,%9}, {%0,%1,%2,%3};"
        : "+f"(c[0]), "+f"(c[1]), "+f"(c[2]), "+f"(c[3])
        : "r"(a[0]), "r"(a[1]), "r"(a[2]), "r"(a[3]), "r"(b0), "r"(b1));
}
__device__ __forceinline__ u32 cvt2(float a, float b) {   // pack (lo=a, hi=b)
    u32 r;
    asm("cvt.rn.bf16x2.f32 %0, %1, %2;" : "=r"(r) : "f"(b), "f"(a));
    return r;
}
__device__ __forceinline__ float bfr(float x) {
    return __bfloat162float(__float2bfloat16(x));
}
__device__ __forceinline__ float fast_tanh(float x) {
    float xc = fminf(fmaxf(x, -10.0f), 10.0f);
    float e = __expf(2.0f * xc);
    return __fdividef(e - 1.0f, e + 1.0f);
}

__global__ void __launch_bounds__(NTHR, 1)
rnn_hmma_m32_kernel(const float* __restrict__ X,
                    const float* __restrict__ Wc,
                    const float* __restrict__ bc,
                    const float* __restrict__ Wo,
                    const float* __restrict__ bo,
                    float* __restrict__ out)
{
    extern __shared__ char smem[];
    const u32 sb = smem_u32(smem);
    const int tid  = threadIdx.x;
    const int lane = tid & 31;
    const int wn   = tid >> 5;         // warp = n-group = SMSP
    const long ctaB0 = (long)blockIdx.x * M_BLK;

    // ================= one-time init =================
    for (int i = tid; i < NPAD * ASTR; i += NTHR) {
        int n = i / ASTR, k = i - n * ASTR;
        float v = (n < H_HID && k < 278) ? Wc[k * H_HID + n] : 0.0f;
        float h = bfr(v);
        u32 off = (u32)n * ASTRB + (u32)k * 2;
        *(__nv_bfloat16*)(smem + SM_WH + off) = __float2bfloat16(h);
        *(__nv_bfloat16*)(smem + SM_WL + off) = __float2bfloat16(v - h);
    }
    for (int n = tid; n < NPAD; n += NTHR)
        *(float*)(smem + SM_BIAS + n * 4) = (n < H_HID) ? bc[n] : 0.0f;
    for (int i = tid * 16; i < 2 * M_BLK * ASTRB; i += NTHR * 16)
        *(float4*)(smem + SM_AH + i) = make_float4(0.f, 0.f, 0.f, 0.f);
    __syncthreads();

    // x loader: each thread owns (row xm, 32 k-values)
    const int xm = tid >> 2;            // 0..31
    const int xk = (tid & 3) * 32;      // 0,32,64,96
    const float* Xrow = X + (ctaB0 + xm) * (long)T_SEQ * D_IN + xk;
    const u32 xdstH = (u32)xm * ASTRB + (u32)xk * 2;
    const u32 xdstL = xdstH + (SM_AL - SM_AH);

    {   // store x(0)
        u32 hh[16], ll[16];
#pragma unroll
        for (int q = 0; q < 8; q++) {
            float4 f = *(const float4*)(Xrow + 4 * q);
            float hx = bfr(f.x), hy = bfr(f.y), hz = bfr(f.z), hw = bfr(f.w);
            hh[2*q] = cvt2(hx, hy); hh[2*q+1] = cvt2(hz, hw);
            ll[2*q] = cvt2(f.x - hx, f.y - hy);
            ll[2*q+1] = cvt2(f.z - hz, f.w - hw);
        }
#pragma unroll
        for (int q = 0; q < 4; q++) {
            *(uint4*)(smem + xdstH + 16 * q) = *(uint4*)&hh[4 * q];
            *(uint4*)(smem + xdstL + 16 * q) = *(uint4*)&ll[4 * q];
        }
    }
    __syncthreads();

    // ============ per-lane ldmatrix bases ============
    const int mat = lane >> 3, r8 = lane & 7;
    // A m-tile bases (mt=0,1): rows 16mt + ((mat&1)<<3) + r8, k-col ((mat>>1)<<3)
    u32 aB[2];
#pragma unroll
    for (int mt = 0; mt < 2; mt++)
        aB[mt] = sb + SM_AH + (u32)(16 * mt + ((mat & 1) << 3) + r8) * ASTRB
                 + (u32)((mat >> 1) << 3) * 2;
    const u32 ALOFF = SM_AL - SM_AH;
    const int nb = 40 * wn;
    const u32 bBase1 = sb + SM_WH + (u32)(nb + ((mat >> 1) << 3) + r8) * ASTRB
                       + (u32)((mat & 1) << 3) * 2;
    const u32 bBase2 = bBase1 + 16 * ASTRB;
    const u32 bBase3 = sb + SM_WH + (u32)(nb + 32 + r8) * ASTRB + (u32)((mat & 1) << 3) * 2;
    const u32 WLOFF = SM_WL - SM_WH;
    const bool has5 = (wn < 3);

    // epilogue mapping + hoisted bias
    const int eg = lane >> 2, et2 = (lane & 3) * 2;
    float2 bias_r[5];
#pragma unroll
    for (int j = 0; j < 5; j++) {
        int n = nb + 8 * j + et2;
        bias_r[j] = (j < 4 || has5) ? *(const float2*)(smem + SM_BIAS + n * 4)
                                    : make_float2(0.f, 0.f);
    }

    // accumulators: c[mt][j][4]
    float c[2][5][4];
#pragma unroll
    for (int mt = 0; mt < 2; mt++)
#pragma unroll
        for (int j = 0; j < 5; j++)
#pragma unroll
            for (int q = 0; q < 4; q++) c[mt][j][q] = 0.0f;

    // fragment double buffers
    u32 fa[2][4][4];    // [buf][ah0,ah1,al0,al1][4]
    u32 fb[2][4][4];    // [buf][bh1,bh2,bl1,bl2][4]
    u32 f5[2][2][2];    // [buf][bh3,bl3][2]

#define LOAD_FRAGS(B, KO)                                                  \
    do {                                                                   \
        ldsm_x4(fa[B][0], aB[0] + (KO));                                   \
        ldsm_x4(fa[B][1], aB[1] + (KO));                                   \
        ldsm_x4(fa[B][2], aB[0] + ALOFF + (KO));                           \
        ldsm_x4(fa[B][3], aB[1] + ALOFF + (KO));                           \
        ldsm_x4(fb[B][0], bBase1 + (KO));                                  \
        ldsm_x4(fb[B][1], bBase2 + (KO));                                  \
        ldsm_x4(fb[B][2], bBase1 + WLOFF + (KO));                          \
        ldsm_x4(fb[B][3], bBase2 + WLOFF + (KO));                          \
        if (has5) {                                                        \
            ldsm_x2(f5[B][0], bBase3 + (KO));                              \
            ldsm_x2(f5[B][1], bBase3 + WLOFF + (KO));                      \
        }                                                                  \
    } while (0)

#define MMA_FRAGS(B)                                                       \
    do {                                                                   \
        /* pass 1: A_hi * B_hi (10 distinct chains) */                     \
        mma16816(c[0][0], fa[B][0], fb[B][0][0], fb[B][0][1]);             \
        mma16816(c[1][0], fa[B][1], fb[B][0][0], fb[B][0][1]);             \
        mma16816(c[0][1], fa[B][0], fb[B][0][2], fb[B][0][3]);             \
        mma16816(c[1][1], fa[B][1], fb[B][0][2], fb[B][0][3]);             \
        mma16816(c[0][2], fa[B][0], fb[B][1][0], fb[B][1][1]);             \
        mma16816(c[1][2], fa[B][1], fb[B][1][0], fb[B][1][1]);             \
        mma16816(c[0][3], fa[B][0], fb[B][1][2], fb[B][1][3]);             \
        mma16816(c[1][3], fa[B][1], fb[B][1][2], fb[B][1][3]);             \
        if (has5) {                                                        \
            mma16816(c[0][4], fa[B][0], f5[B][0][0], f5[B][0][1]);         \
            mma16816(c[1][4], fa[B][1], f5[B][0][0], f5[B][0][1]);         \
        }                                                                  \
        /* pass 2: A_hi * B_lo */                                          \
        mma16816(c[0][0], fa[B][0], fb[B][2][0], fb[B][2][1]);             \
        mma16816(c[1][0], fa[B][1], fb[B][2][0], fb[B][2][1]);             \
        mma16816(c[0][1], fa[B][0], fb[B][2][2], fb[B][2][3]);             \
        mma16816(c[1][1], fa[B][1], fb[B][2][2], fb[B][2][3]);             \
        mma16816(c[0][2], fa[B][0], fb[B][3][0], fb[B][3][1]);             \
        mma16816(c[1][2], fa[B][1], fb[B][3][0], fb[B][3][1]);             \
        mma16816(c[0][3], fa[B][0], fb[B][3][2], fb[B][3][3]);             \
        mma16816(c[1][3], fa[B][1], fb[B][3][2], fb[B][3][3]);             \
        if (has5) {                                                        \
            mma16816(c[0][4], fa[B][0], f5[B][1][0], f5[B][1][1]);         \
            mma16816(c[1][4], fa[B][1], f5[B][1][0], f5[B][1][1]);         \
        }                                                                  \
        /* pass 3: A_lo * B_hi */                                          \
        mma16816(c[0][0], fa[B][2], fb[B][0][0], fb[B][0][1]);             \
        mma16816(c[1][0], fa[B][3], fb[B][0][0], fb[B][0][1]);             \
        mma16816(c[0][1], fa[B][2], fb[B][0][2], fb[B][0][3]);             \
        mma16816(c[1][1], fa[B][3], fb[B][0][2], fb[B][0][3]);             \
        mma16816(c[0][2], fa[B][2], fb[B][1][0], fb[B][1][1]);             \
        mma16816(c[1][2], fa[B][3], fb[B][1][0], fb[B][1][1]);             \
        mma16816(c[0][3], fa[B][2], fb[B][1][2], fb[B][1][3]);             \
        mma16816(c[1][3], fa[B][3], fb[B][1][2], fb[B][1][3]);             \
        if (has5) {                                                        \
            mma16816(c[0][4], fa[B][2], f5[B][0][0], f5[B][0][1]);         \
            mma16816(c[1][4], fa[B][3], f5[B][0][0], f5[B][0][1]);         \
        }                                                                  \
    } while (0)

    // ================= time loop =================
    for (int t = 0; t < T_SEQ; t++) {
        // prefetch x(t+1)
        float4 v[8];
        const bool havex = (t + 1 < T_SEQ);
        if (havex) {
            const float* xp = Xrow + (long)(t + 1) * D_IN;
#pragma unroll
            for (int q = 0; q < 8; q++) v[q] = *(const float4*)(xp + 4 * q);
        }

        // ---- K loop, software-pipelined fragments ----
        LOAD_FRAGS(0, 0u);
#pragma unroll
        for (int kt = 0; kt < KTILES; kt++) {
            const int cur = kt & 1;
            if (kt + 1 < KTILES) LOAD_FRAGS(!cur ? 1 : 0, (u32)(kt + 1) * 32);
            MMA_FRAGS(cur);
        }

        __syncthreads();   // (A) all ldmatrix reads of A done

        // ---- epilogue: h = tanh(acc + bias) -> AH/AL, reset acc ----
#pragma unroll
        for (int mt = 0; mt < 2; mt++) {
            const int em = 16 * mt + eg;
#pragma unroll
            for (int j = 0; j < 5; j++) {
                if (j == 4 && !has5) break;
                const int n = nb + 8 * j + et2;
                float h00 = fast_tanh(c[mt][j][0] + bias_r[j].x);
                float h01 = fast_tanh(c[mt][j][1] + bias_r[j].y);
                float h10 = fast_tanh(c[mt][j][2] + bias_r[j].x);
                float h11 = fast_tanh(c[mt][j][3] + bias_r[j].y);
                float r00 = bfr(h00), r01 = bfr(h01), r10 = bfr(h10), r11 = bfr(h11);
                u32 o0 = (u32)em * ASTRB + (u32)(D_IN + n) * 2;
                u32 o1 = o0 + 8 * ASTRB;
                *(u32*)(smem + SM_AH + o0) = cvt2(h00, h01);
                *(u32*)(smem + SM_AH + o1) = cvt2(h10, h11);
                *(u32*)(smem + SM_AL + o0) = cvt2(h00 - r00, h01 - r01);
                *(u32*)(smem + SM_AL + o1) = cvt2(h10 - r10, h11 - r11);
                c[mt][j][0] = 0.f; c[mt][j][1] = 0.f;
                c[mt][j][2] = 0.f; c[mt][j][3] = 0.f;
            }
        }

        // ---- store prefetched x(t+1) ----
        if (havex) {
            u32 hh[16], ll[16];
#pragma unroll
            for (int q = 0; q < 8; q++) {
                float hx = bfr(v[q].x), hy = bfr(v[q].y), hz = bfr(v[q].z), hw = bfr(v[q].w);
                hh[2*q] = cvt2(hx, hy); hh[2*q+1] = cvt2(hz, hw);
                ll[2*q] = cvt2(v[q].x - hx, v[q].y - hy);
                ll[2*q+1] = cvt2(v[q].z - hz, v[q].w - hw);
            }
#pragma unroll
            for (int q = 0; q < 4; q++) {
                *(uint4*)(smem + xdstH + 16 * q) = *(uint4*)&hh[4 * q];
                *(uint4*)(smem + xdstL + 16 * q) = *(uint4*)&ll[4 * q];
            }
        }
        __syncthreads();   // (B) h(t) + x(t+1) visible
    }

    // ================= classifier head =================
    for (int i = tid; i < M_BLK * O_OUT; i += NTHR) {
        const int b = i / O_OUT;
        const int o = i - b * O_OUT;
        float s = bo[o];
        const char* rowH = smem + SM_AH + (u32)b * ASTRB + D_IN * 2;
        const char* rowL = smem + SM_AL + (u32)b * ASTRB + D_IN * 2;
#pragma unroll 5
        for (int j = 0; j < H_HID; j++) {
            float hv = __bfloat162float(*(const __nv_bfloat16*)(rowH + 2 * j))
                     + __bfloat162float(*(const __nv_bfloat16*)(rowL + 2 * j));
            s += hv * Wo[j * O_OUT + o];
        }
        out[(ctaB0 + b) * O_OUT + o] = s;
    }
}

extern "C" void kernel_launch(void* const* d_in, const int* in_sizes, int n_in,
                              void* d_out, int out_size)
{
    const float* X  = (const float*)d_in[0];
    const float* Wc = (const float*)d_in[1];
    const float* bc = (const float*)d_in[2];
    const float* Wo = (const float*)d_in[3];
    const float* bo = (const float*)d_in[4];
    float* out = (float*)d_out;

    const int B = in_sizes[0] / (T_SEQ * D_IN);   // 4096

    cudaFuncSetAttribute(rnn_hmma_m32_kernel,
                         cudaFuncAttributeMaxDynamicSharedMemorySize, SMEM_BYTES);

    rnn_hmma_m32_kernel<<<B / M_BLK, NTHR, SMEM_BYTES>>>(X, Wc, bc, Wo, bo, out);
}

// round 10
// speedup vs baseline: 3.1066x; 3.1066x over previous
#include <cuda_runtime.h>
#include <cuda_fp16.h>
#include <cstdint>

// RNN h_t = tanh([x_t,h_{t-1}]@Wc + bc); out = h_T@Wo + bo
// B=4096, T=128, D=128, H=150, O=10.
// R10: SINGLE-PASS fp16 mma.sync.m16n8k16 (fp32 acc). 8 warps (256 thr),
// each warp owns m32 x 2-3 n8-tiles (5 n8/SMSP balanced), frag double-buffer.
// Head uses an fp32 h stash written at the last step.

#define T_SEQ 128
#define D_IN  128
#define H_HID 150
#define O_OUT 10
#define M_BLK 32
#define NPAD  160            // 20 n8-tiles
#define KTILES 18            // K = 288
#define ASTR  296            // row stride in fp16 elems (592 B, ldmatrix conflict-free)
#define ASTRB 592
#define NTHR  256

// SMEM byte offsets
#define SM_A    0
#define SM_W    18944                  // +32*592
#define SM_BIAS 113664                 // +160*592
#define SM_HF   114304                 // +160*4 ; fp32 h stash [32][160]
#define SMEM_BYTES 134784              // +32*640

typedef unsigned int u32;

__device__ __forceinline__ u32 smem_u32(const void* p) {
    u32 a;
    asm("{ .reg .u64 t; cvta.to.shared.u64 t, %1; cvt.u32.u64 %0, t; }" : "=r"(a) : "l"(p));
    return a;
}
__device__ __forceinline__ void ldsm_x4(u32* r, u32 addr) {
    asm volatile("ldmatrix.sync.aligned.m8n8.x4.shared.b16 {%0,%1,%2,%3}, [%4];"
        : "=r"(r[0]), "=r"(r[1]), "=r"(r[2]), "=r"(r[3]) : "r"(addr));
}
__device__ __forceinline__ void ldsm_x2(u32* r, u32 addr) {
    asm volatile("ldmatrix.sync.aligned.m8n8.x2.shared.b16 {%0,%1}, [%2];"
        : "=r"(r[0]), "=r"(r[1]) : "r"(addr));
}
__device__ __forceinline__ void mma_f16(float* c, const u32* a, u32 b0, u32 b1) {
    asm volatile("mma.sync.aligned.m16n8k16.row.col.f32.f16.f16.f32 "
        "{%0,%1,%2,%3}, {%4,%5,%6,%7}, {%8,%9}, {%0,%1,%2,%3};"
        : "+f"(c[0]), "+f"(c[1]), "+f"(c[2]), "+f"(c[3])
        : "r"(a[0]), "r"(a[1]), "r"(a[2]), "r"(a[3]), "r"(b0), "r"(b1));
}
__device__ __forceinline__ u32 cvt2h(float a, float b) {   // pack fp16x2 (lo=a, hi=b)
    u32 r;
    asm("cvt.rn.f16x2.f32 %0, %1, %2;" : "=r"(r) : "f"(b), "f"(a));
    return r;
}
__device__ __forceinline__ float fast_tanh(float x) {
    float xc = fminf(fmaxf(x, -10.0f), 10.0f);
    float e = __expf(2.0f * xc);
    return __fdividef(e - 1.0f, e + 1.0f);
}

__global__ void __launch_bounds__(NTHR, 1)
rnn_f16_1p_kernel(const float* __restrict__ X,
                  const float* __restrict__ Wc,
                  const float* __restrict__ bc,
                  const float* __restrict__ Wo,
                  const float* __restrict__ bo,
                  float* __restrict__ out)
{
    extern __shared__ char smem[];
    const u32 sb = smem_u32(smem);
    const int tid  = threadIdx.x;
    const int lane = tid & 31;
    const int w    = tid >> 5;
    const long ctaB0 = (long)blockIdx.x * M_BLK;

    // warp -> n-tile range (start s_tab[w], count 2 or 3); 5 n8-tiles per SMSP
    const int s_tab[8] = {0, 3, 5, 8, 10, 12, 15, 17};
    const int s   = s_tab[w];
    const bool nt3 = (w == 0) | (w == 2) | (w == 5) | (w == 7);

    // ================= one-time init =================
    // W^T fp16: row n (0..159), col k (0..295); valid (n<150, k<278) else 0
    for (int i = tid; i < NPAD * ASTR; i += NTHR) {
        int n = i / ASTR, k = i - n * ASTR;
        float v = (n < H_HID && k < 278) ? Wc[k * H_HID + n] : 0.0f;
        *(__half*)(smem + SM_W + (u32)n * ASTRB + (u32)k * 2) = __float2half_rn(v);
    }
    for (int n = tid; n < NPAD; n += NTHR)
        *(float*)(smem + SM_BIAS + n * 4) = (n < H_HID) ? bc[n] : 0.0f;
    // zero A (x region overwritten; h region must start 0; k-pad stays 0)
    for (int i = tid * 16; i < M_BLK * ASTRB; i += NTHR * 16)
        *(float4*)(smem + SM_A + i) = make_float4(0.f, 0.f, 0.f, 0.f);
    __syncthreads();

    // x loader: each thread owns (row xm, 16 k-values)
    const int xm = tid >> 3;            // 0..31
    const int xk = (tid & 7) * 16;      // 0..112
    const float* Xrow = X + (ctaB0 + xm) * (long)T_SEQ * D_IN + xk;
    const u32 xdst = (u32)xm * ASTRB + (u32)xk * 2;

    {   // store x(0)
        u32 hh[8];
#pragma unroll
        for (int q = 0; q < 4; q++) {
            float4 f = *(const float4*)(Xrow + 4 * q);
            hh[2*q]   = cvt2h(f.x, f.y);
            hh[2*q+1] = cvt2h(f.z, f.w);
        }
        *(uint4*)(smem + SM_A + xdst)      = *(uint4*)&hh[0];
        *(uint4*)(smem + SM_A + xdst + 16) = *(uint4*)&hh[4];
    }
    __syncthreads();

    // ============ per-lane ldmatrix bases ============
    const int mat = lane >> 3, r8 = lane & 7;
    // A m-tiles (mt=0,1): mats {m0-7@k0, m8-15@k0, m0-7@k8, m8-15@k8}
    u32 aB[2];
#pragma unroll
    for (int mt = 0; mt < 2; mt++)
        aB[mt] = sb + SM_A + (u32)(16 * mt + ((mat & 1) << 3) + r8) * ASTRB
                 + (u32)((mat >> 1) << 3) * 2;
    // B tiles s,s+1 via x4: mats {n0-7@k0, n0-7@k8, n8-15@k0, n8-15@k8}
    const u32 bB4 = sb + SM_W + (u32)(8 * s + ((mat >> 1) << 3) + r8) * ASTRB
                    + (u32)((mat & 1) << 3) * 2;
    // B tile s+2 via x2: mats {@k0, @k8}
    const u32 bB2 = sb + SM_W + (u32)(8 * (s + 2) + r8) * ASTRB
                    + (u32)((mat & 1) << 3) * 2;

    // epilogue mapping + hoisted bias
    const int eg = lane >> 2, et2 = (lane & 3) * 2;
    float2 bias_r[3];
#pragma unroll
    for (int j = 0; j < 3; j++)
        bias_r[j] = *(const float2*)(smem + SM_BIAS + (8 * (s + j) + et2) * 4);

    float c[2][3][4];
#pragma unroll
    for (int mt = 0; mt < 2; mt++)
#pragma unroll
        for (int j = 0; j < 3; j++)
#pragma unroll
            for (int q = 0; q < 4; q++) c[mt][j][q] = 0.0f;

    // fragment double buffers
    u32 fa[2][2][4];     // [buf][mt][4]
    u32 fb[2][4];        // [buf][4]  tiles s, s+1
    u32 f3[2][2];        // [buf][2]  tile s+2

#define LOADF(B, KO)                         \
    do {                                     \
        ldsm_x4(fa[B][0], aB[0] + (KO));     \
        ldsm_x4(fa[B][1], aB[1] + (KO));     \
        ldsm_x4(fb[B],    bB4   + (KO));     \
        if (nt3) ldsm_x2(f3[B], bB2 + (KO)); \
    } while (0)

#define MMAF(B)                                              \
    do {                                                     \
        mma_f16(c[0][0], fa[B][0], fb[B][0], fb[B][1]);      \
        mma_f16(c[1][0], fa[B][1], fb[B][0], fb[B][1]);      \
        mma_f16(c[0][1], fa[B][0], fb[B][2], fb[B][3]);      \
        mma_f16(c[1][1], fa[B][1], fb[B][2], fb[B][3]);      \
        if (nt3) {                                           \
            mma_f16(c[0][2], fa[B][0], f3[B][0], f3[B][1]);  \
            mma_f16(c[1][2], fa[B][1], f3[B][0], f3[B][1]);  \
        }                                                    \
    } while (0)

    // ================= time loop =================
    for (int t = 0; t < T_SEQ; t++) {
        // prefetch x(t+1)
        float4 v[4];
        const bool havex = (t + 1 < T_SEQ);
        if (havex) {
            const float* xp = Xrow + (long)(t + 1) * D_IN;
#pragma unroll
            for (int q = 0; q < 4; q++) v[q] = *(const float4*)(xp + 4 * q);
        }

        // ---- K loop, double-buffered ----
        LOADF(0, 0u);
#pragma unroll
        for (int kt = 0; kt < KTILES; kt++) {
            const int cur = kt & 1;
            if (kt + 1 < KTILES) LOADF(cur ^ 1, (u32)(kt + 1) * 32);
            MMAF(cur);
        }

        __syncthreads();   // (A) all ldmatrix reads of A done

        // ---- epilogue: h = tanh(acc + bias) -> A fp16; last step also fp32 ----
        const bool last = (t == T_SEQ - 1);
#pragma unroll
        for (int mt = 0; mt < 2; mt++) {
            const int em = 16 * mt + eg;
#pragma unroll
            for (int j = 0; j < 3; j++) {
                if (j == 2 && !nt3) break;
                const int n = 8 * (s + j) + et2;
                float h00 = fast_tanh(c[mt][j][0] + bias_r[j].x);
                float h01 = fast_tanh(c[mt][j][1] + bias_r[j].y);
                float h10 = fast_tanh(c[mt][j][2] + bias_r[j].x);
                float h11 = fast_tanh(c[mt][j][3] + bias_r[j].y);
                u32 o0 = (u32)em * ASTRB + (u32)(D_IN + n) * 2;
                u32 o1 = o0 + 8 * ASTRB;
                *(u32*)(smem + SM_A + o0) = cvt2h(h00, h01);
                *(u32*)(smem + SM_A + o1) = cvt2h(h10, h11);
                if (last) {
                    *(float2*)(smem + SM_HF + ((u32)em * NPAD + n) * 4)
                        = make_float2(h00, h01);
                    *(float2*)(smem + SM_HF + ((u32)(em + 8) * NPAD + n) * 4)
                        = make_float2(h10, h11);
                }
                c[mt][j][0] = 0.f; c[mt][j][1] = 0.f;
                c[mt][j][2] = 0.f; c[mt][j][3] = 0.f;
            }
        }

        // ---- store prefetched x(t+1) ----
        if (havex) {
            u32 hh[8];
#pragma unroll
            for (int q = 0; q < 4; q++) {
                hh[2*q]   = cvt2h(v[q].x, v[q].y);
                hh[2*q+1] = cvt2h(v[q].z, v[q].w);
            }
            *(uint4*)(smem + SM_A + xdst)      = *(uint4*)&hh[0];
            *(uint4*)(smem + SM_A + xdst + 16) = *(uint4*)&hh[4];
        }
        __syncthreads();   // (B) h(t) + x(t+1) visible
    }

    // ================= classifier head (fp32 h stash) =================
    for (int i = tid; i < M_BLK * O_OUT; i += NTHR) {
        const int b = i / O_OUT;
        const int o = i - b * O_OUT;
        float sacc = bo[o];
        const float* hrow = (const float*)(smem + SM_HF + (u32)b * NPAD * 4);
#pragma unroll 5
        for (int j = 0; j < H_HID; j++)
            sacc += hrow[j] * Wo[j * O_OUT + o];
        out[(ctaB0 + b) * O_OUT + o] = sacc;
    }
}

extern "C" void kernel_launch(void* const* d_in, const int* in_sizes, int n_in,
                              void* d_out, int out_size)
{
    const float* X  = (const float*)d_in[0];
    const float* Wc = (const float*)d_in[1];
    const float* bc = (const float*)d_in[2];
    const float* Wo = (const float*)d_in[3];
    const float* bo = (const float*)d_in[4];
    float* out = (float*)d_out;

    const int B = in_sizes[0] / (T_SEQ * D_IN);   // 4096

    cudaFuncSetAttribute(rnn_f16_1p_kernel,
                         cudaFuncAttributeMaxDynamicSharedMemorySize, SMEM_BYTES);

    rnn_f16_1p_kernel<<<B / M_BLK, NTHR, SMEM_BYTES>>>(X, Wc, bc, Wo, bo, out);
}

// round 11
// speedup vs baseline: 3.8373x; 1.2352x over previous
#include <cuda_runtime.h>
#include <cuda_fp16.h>
#include <cstdint>

// RNN h_t = tanh([x_t,h_{t-1}]@Wc + bc); out = h_T@Wo + bo
// B=4096, T=128, D=128, H=150, O=10.
// R11: single-pass fp16 mma.sync, 8 warps, and ALL weight (B) fragments are
// pre-loaded into registers before the time loop (W constant across t).
// Inner loop LDS traffic = A-fragments only.

#define T_SEQ 128
#define D_IN  128
#define H_HID 150
#define O_OUT 10
#define M_BLK 32
#define NPAD  160            // 20 n8-tiles
#define KTILES 18            // K = 288
#define ASTR  296            // row stride in fp16 elems (592 B, ldmatrix conflict-free)
#define ASTRB 592
#define NTHR  256

// SMEM byte offsets
#define SM_A    0
#define SM_W    18944                  // +32*592
#define SM_BIAS 113664                 // +160*592
#define SM_HF   114304                 // +160*4 ; fp32 h stash [32][160]
#define SMEM_BYTES 134784              // +32*640

typedef unsigned int u32;

__device__ __forceinline__ u32 smem_u32(const void* p) {
    u32 a;
    asm("{ .reg .u64 t; cvta.to.shared.u64 t, %1; cvt.u32.u64 %0, t; }" : "=r"(a) : "l"(p));
    return a;
}
__device__ __forceinline__ void ldsm_x4(u32* r, u32 addr) {
    asm volatile("ldmatrix.sync.aligned.m8n8.x4.shared.b16 {%0,%1,%2,%3}, [%4];"
        : "=r"(r[0]), "=r"(r[1]), "=r"(r[2]), "=r"(r[3]) : "r"(addr));
}
__device__ __forceinline__ void ldsm_x2(u32* r, u32 addr) {
    asm volatile("ldmatrix.sync.aligned.m8n8.x2.shared.b16 {%0,%1}, [%2];"
        : "=r"(r[0]), "=r"(r[1]) : "r"(addr));
}
__device__ __forceinline__ void mma_f16(float* c, const u32* a, u32 b0, u32 b1) {
    asm volatile("mma.sync.aligned.m16n8k16.row.col.f32.f16.f16.f32 "
        "{%0,%1,%2,%3}, {%4,%5,%6,%7}, {%8,%9}, {%0,%1,%2,%3};"
        : "+f"(c[0]), "+f"(c[1]), "+f"(c[2]), "+f"(c[3])
        : "r"(a[0]), "r"(a[1]), "r"(a[2]), "r"(a[3]), "r"(b0), "r"(b1));
}
__device__ __forceinline__ u32 cvt2h(float a, float b) {   // pack fp16x2 (lo=a, hi=b)
    u32 r;
    asm("cvt.rn.f16x2.f32 %0, %1, %2;" : "=r"(r) : "f"(b), "f"(a));
    return r;
}
__device__ __forceinline__ float fast_tanh(float x) {
    float xc = fminf(fmaxf(x, -10.0f), 10.0f);
    float e = __expf(2.0f * xc);
    return __fdividef(e - 1.0f, e + 1.0f);
}

__global__ void __launch_bounds__(NTHR, 1)
rnn_f16_wreg_kernel(const float* __restrict__ X,
                    const float* __restrict__ Wc,
                    const float* __restrict__ bc,
                    const float* __restrict__ Wo,
                    const float* __restrict__ bo,
                    float* __restrict__ out)
{
    extern __shared__ char smem[];
    const u32 sb = smem_u32(smem);
    const int tid  = threadIdx.x;
    const int lane = tid & 31;
    const int w    = tid >> 5;
    const long ctaB0 = (long)blockIdx.x * M_BLK;

    // warp -> n-tile range (start s_tab[w], count 2 or 3)
    const int s_tab[8] = {0, 3, 5, 8, 10, 12, 15, 17};
    const int s   = s_tab[w];
    const bool nt3 = (w == 0) | (w == 2) | (w == 5) | (w == 7);

    // ================= one-time init =================
    for (int i = tid; i < NPAD * ASTR; i += NTHR) {
        int n = i / ASTR, k = i - n * ASTR;
        float v = (n < H_HID && k < 278) ? Wc[k * H_HID + n] : 0.0f;
        *(__half*)(smem + SM_W + (u32)n * ASTRB + (u32)k * 2) = __float2half_rn(v);
    }
    for (int n = tid; n < NPAD; n += NTHR)
        *(float*)(smem + SM_BIAS + n * 4) = (n < H_HID) ? bc[n] : 0.0f;
    for (int i = tid * 16; i < M_BLK * ASTRB; i += NTHR * 16)
        *(float4*)(smem + SM_A + i) = make_float4(0.f, 0.f, 0.f, 0.f);
    __syncthreads();

    // x loader: each thread owns (row xm, 16 k-values)
    const int xm = tid >> 3;
    const int xk = (tid & 7) * 16;
    const float* Xrow = X + (ctaB0 + xm) * (long)T_SEQ * D_IN + xk;
    const u32 xdst = (u32)xm * ASTRB + (u32)xk * 2;

    {   // store x(0)
        u32 hh[8];
#pragma unroll
        for (int q = 0; q < 4; q++) {
            float4 f = *(const float4*)(Xrow + 4 * q);
            hh[2*q]   = cvt2h(f.x, f.y);
            hh[2*q+1] = cvt2h(f.z, f.w);
        }
        *(uint4*)(smem + SM_A + xdst)      = *(uint4*)&hh[0];
        *(uint4*)(smem + SM_A + xdst + 16) = *(uint4*)&hh[4];
    }

    // ============ per-lane ldmatrix bases ============
    const int mat = lane >> 3, r8 = lane & 7;
    u32 aB[2];
#pragma unroll
    for (int mt = 0; mt < 2; mt++)
        aB[mt] = sb + SM_A + (u32)(16 * mt + ((mat & 1) << 3) + r8) * ASTRB
                 + (u32)((mat >> 1) << 3) * 2;
    const u32 bB4 = sb + SM_W + (u32)(8 * s + ((mat >> 1) << 3) + r8) * ASTRB
                    + (u32)((mat & 1) << 3) * 2;
    const u32 bB2 = sb + SM_W + (u32)(8 * (s + 2) + r8) * ASTRB
                    + (u32)((mat & 1) << 3) * 2;

    // ---- PRE-LOAD ALL B (weight) FRAGMENTS INTO REGISTERS ----
    u32 wb[KTILES][4];     // tiles s, s+1
    u32 w3[KTILES][2];     // tile s+2 (nt3 warps)
#pragma unroll
    for (int kt = 0; kt < KTILES; kt++) {
        ldsm_x4(wb[kt], bB4 + (u32)kt * 32);
        if (nt3) ldsm_x2(w3[kt], bB2 + (u32)kt * 32);
    }
    __syncthreads();   // x(0) stores + W reads complete

    // epilogue mapping + hoisted bias
    const int eg = lane >> 2, et2 = (lane & 3) * 2;
    float2 bias_r[3];
#pragma unroll
    for (int j = 0; j < 3; j++)
        bias_r[j] = *(const float2*)(smem + SM_BIAS + (8 * (s + j) + et2) * 4);

    float c[2][3][4];
#pragma unroll
    for (int mt = 0; mt < 2; mt++)
#pragma unroll
        for (int j = 0; j < 3; j++)
#pragma unroll
            for (int q = 0; q < 4; q++) c[mt][j][q] = 0.0f;

    // A fragment double buffer
    u32 fa[2][2][4];

#define LOADA(B, KO)                         \
    do {                                     \
        ldsm_x4(fa[B][0], aB[0] + (KO));     \
        ldsm_x4(fa[B][1], aB[1] + (KO));     \
    } while (0)

#define MMAF(B, KT)                                                 \
    do {                                                            \
        mma_f16(c[0][0], fa[B][0], wb[KT][0], wb[KT][1]);           \
        mma_f16(c[1][0], fa[B][1], wb[KT][0], wb[KT][1]);           \
        mma_f16(c[0][1], fa[B][0], wb[KT][2], wb[KT][3]);           \
        mma_f16(c[1][1], fa[B][1], wb[KT][2], wb[KT][3]);           \
        if (nt3) {                                                  \
            mma_f16(c[0][2], fa[B][0], w3[KT][0], w3[KT][1]);       \
            mma_f16(c[1][2], fa[B][1], w3[KT][0], w3[KT][1]);       \
        }                                                           \
    } while (0)

    // ================= time loop =================
    for (int t = 0; t < T_SEQ; t++) {
        // prefetch x(t+1)
        float4 v[4];
        const bool havex = (t + 1 < T_SEQ);
        if (havex) {
            const float* xp = Xrow + (long)(t + 1) * D_IN;
#pragma unroll
            for (int q = 0; q < 4; q++) v[q] = *(const float4*)(xp + 4 * q);
        }

        // ---- K loop: A double-buffered, B from registers ----
        LOADA(0, 0u);
#pragma unroll
        for (int kt = 0; kt < KTILES; kt++) {
            const int cur = kt & 1;
            if (kt + 1 < KTILES) LOADA(cur ^ 1, (u32)(kt + 1) * 32);
            MMAF(cur, kt);
        }

        __syncthreads();   // (A) all ldmatrix reads of A done

        // ---- epilogue: h = tanh(acc + bias) -> A fp16; last step also fp32 ----
        const bool last = (t == T_SEQ - 1);
#pragma unroll
        for (int mt = 0; mt < 2; mt++) {
            const int em = 16 * mt + eg;
#pragma unroll
            for (int j = 0; j < 3; j++) {
                if (j == 2 && !nt3) break;
                const int n = 8 * (s + j) + et2;
                float h00 = fast_tanh(c[mt][j][0] + bias_r[j].x);
                float h01 = fast_tanh(c[mt][j][1] + bias_r[j].y);
                float h10 = fast_tanh(c[mt][j][2] + bias_r[j].x);
                float h11 = fast_tanh(c[mt][j][3] + bias_r[j].y);
                u32 o0 = (u32)em * ASTRB + (u32)(D_IN + n) * 2;
                u32 o1 = o0 + 8 * ASTRB;
                *(u32*)(smem + SM_A + o0) = cvt2h(h00, h01);
                *(u32*)(smem + SM_A + o1) = cvt2h(h10, h11);
                if (last) {
                    *(float2*)(smem + SM_HF + ((u32)em * NPAD + n) * 4)
                        = make_float2(h00, h01);
                    *(float2*)(smem + SM_HF + ((u32)(em + 8) * NPAD + n) * 4)
                        = make_float2(h10, h11);
                }
                c[mt][j][0] = 0.f; c[mt][j][1] = 0.f;
                c[mt][j][2] = 0.f; c[mt][j][3] = 0.f;
            }
        }

        // ---- store prefetched x(t+1) ----
        if (havex) {
            u32 hh[8];
#pragma unroll
            for (int q = 0; q < 4; q++) {
                hh[2*q]   = cvt2h(v[q].x, v[q].y);
                hh[2*q+1] = cvt2h(v[q].z, v[q].w);
            }
            *(uint4*)(smem + SM_A + xdst)      = *(uint4*)&hh[0];
            *(uint4*)(smem + SM_A + xdst + 16) = *(uint4*)&hh[4];
        }
        __syncthreads();   // (B) h(t) + x(t+1) visible
    }

    // ================= classifier head (fp32 h stash) =================
    for (int i = tid; i < M_BLK * O_OUT; i += NTHR) {
        const int b = i / O_OUT;
        const int o = i - b * O_OUT;
        float sacc = bo[o];
        const float* hrow = (const float*)(smem + SM_HF + (u32)b * NPAD * 4);
#pragma unroll 5
        for (int j = 0; j < H_HID; j++)
            sacc += hrow[j] * Wo[j * O_OUT + o];
        out[(ctaB0 + b) * O_OUT + o] = sacc;
    }
}

extern "C" void kernel_launch(void* const* d_in, const int* in_sizes, int n_in,
                              void* d_out, int out_size)
{
    const float* X  = (const float*)d_in[0];
    const float* Wc = (const float*)d_in[1];
    const float* bc = (const float*)d_in[2];
    const float* Wo = (const float*)d_in[3];
    const float* bo = (const float*)d_in[4];
    float* out = (float*)d_out;

    const int B = in_sizes[0] / (T_SEQ * D_IN);   // 4096

    cudaFuncSetAttribute(rnn_f16_wreg_kernel,
                         cudaFuncAttributeMaxDynamicSharedMemorySize, SMEM_BYTES);

    rnn_f16_wreg_kernel<<<B / M_BLK, NTHR, SMEM_BYTES>>>(X, Wc, bc, Wo, bo, out);
}

// round 12
// speedup vs baseline: 4.3686x; 1.1384x over previous
#include <cuda_runtime.h>
#include <cuda_fp16.h>
#include <cstdint>

// RNN h_t = tanh([x_t,h_{t-1}]@Wc + bc); out = h_T@Wo + bo
// B=4096, T=128, D=128, H=150, O=10.
// R12: single-pass fp16 mma.sync, weights in registers (R11), plus:
//  - A operand double-buffered -> only ONE __syncthreads per timestep
//  - hardware tanh (tanh.approx.f32, MUFU.TANH)

#define T_SEQ 128
#define D_IN  128
#define H_HID 150
#define O_OUT 10
#define M_BLK 32
#define NPAD  160            // 20 n8-tiles
#define KTILES 18            // K = 288
#define ASTR  296            // row stride in fp16 elems (592 B, ldmatrix conflict-free)
#define ASTRB 592
#define NTHR  256

// SMEM byte offsets
#define SM_A0   0
#define ABUFSZ  18944                  // 32*592
#define SM_A1   18944
#define SM_W    37888                  // +32*592
#define SM_BIAS 132608                 // +160*592
#define SM_HF   133248                 // +640 ; fp32 h stash [32][160]
#define SMEM_BYTES 153728              // +32*640

typedef unsigned int u32;

__device__ __forceinline__ u32 smem_u32(const void* p) {
    u32 a;
    asm("{ .reg .u64 t; cvta.to.shared.u64 t, %1; cvt.u32.u64 %0, t; }" : "=r"(a) : "l"(p));
    return a;
}
__device__ __forceinline__ void ldsm_x4(u32* r, u32 addr) {
    asm volatile("ldmatrix.sync.aligned.m8n8.x4.shared.b16 {%0,%1,%2,%3}, [%4];"
        : "=r"(r[0]), "=r"(r[1]), "=r"(r[2]), "=r"(r[3]) : "r"(addr));
}
__device__ __forceinline__ void ldsm_x2(u32* r, u32 addr) {
    asm volatile("ldmatrix.sync.aligned.m8n8.x2.shared.b16 {%0,%1}, [%2];"
        : "=r"(r[0]), "=r"(r[1]) : "r"(addr));
}
__device__ __forceinline__ void mma_f16(float* c, const u32* a, u32 b0, u32 b1) {
    asm volatile("mma.sync.aligned.m16n8k16.row.col.f32.f16.f16.f32 "
        "{%0,%1,%2,%3}, {%4,%5,%6,%7}, {%8,%9}, {%0,%1,%2,%3};"
        : "+f"(c[0]), "+f"(c[1]), "+f"(c[2]), "+f"(c[3])
        : "r"(a[0]), "r"(a[1]), "r"(a[2]), "r"(a[3]), "r"(b0), "r"(b1));
}
__device__ __forceinline__ u32 cvt2h(float a, float b) {   // pack fp16x2 (lo=a, hi=b)
    u32 r;
    asm("cvt.rn.f16x2.f32 %0, %1, %2;" : "=r"(r) : "f"(b), "f"(a));
    return r;
}
__device__ __forceinline__ float htanh(float x) {          // MUFU.TANH
    float r;
    asm("tanh.approx.f32 %0, %1;" : "=f"(r) : "f"(x));
    return r;
}

__global__ void __launch_bounds__(NTHR, 1)
rnn_f16_db_kernel(const float* __restrict__ X,
                  const float* __restrict__ Wc,
                  const float* __restrict__ bc,
                  const float* __restrict__ Wo,
                  const float* __restrict__ bo,
                  float* __restrict__ out)
{
    extern __shared__ char smem[];
    const u32 sb = smem_u32(smem);
    const int tid  = threadIdx.x;
    const int lane = tid & 31;
    const int w    = tid >> 5;
    const long ctaB0 = (long)blockIdx.x * M_BLK;

    // warp -> n-tile range (start s_tab[w], count 2 or 3)
    const int s_tab[8] = {0, 3, 5, 8, 10, 12, 15, 17};
    const int s   = s_tab[w];
    const bool nt3 = (w == 0) | (w == 2) | (w == 5) | (w == 7);

    // ================= one-time init =================
    for (int i = tid; i < NPAD * ASTR; i += NTHR) {
        int n = i / ASTR, k = i - n * ASTR;
        float v = (n < H_HID && k < 278) ? Wc[k * H_HID + n] : 0.0f;
        *(__half*)(smem + SM_W + (u32)n * ASTRB + (u32)k * 2) = __float2half_rn(v);
    }
    for (int n = tid; n < NPAD; n += NTHR)
        *(float*)(smem + SM_BIAS + n * 4) = (n < H_HID) ? bc[n] : 0.0f;
    // zero A buffer 0 (x overwritten below; h region must start as 0)
    for (int i = tid * 16; i < M_BLK * ASTRB; i += NTHR * 16)
        *(float4*)(smem + SM_A0 + i) = make_float4(0.f, 0.f, 0.f, 0.f);
    __syncthreads();

    // x loader: each thread owns (row xm, 16 k-values)
    const int xm = tid >> 3;
    const int xk = (tid & 7) * 16;
    const float* Xrow = X + (ctaB0 + xm) * (long)T_SEQ * D_IN + xk;
    const u32 xdst = (u32)xm * ASTRB + (u32)xk * 2;   // relative to A buffer base

    {   // store x(0) -> buf0
        u32 hh[8];
#pragma unroll
        for (int q = 0; q < 4; q++) {
            float4 f = *(const float4*)(Xrow + 4 * q);
            hh[2*q]   = cvt2h(f.x, f.y);
            hh[2*q+1] = cvt2h(f.z, f.w);
        }
        *(uint4*)(smem + SM_A0 + xdst)      = *(uint4*)&hh[0];
        *(uint4*)(smem + SM_A0 + xdst + 16) = *(uint4*)&hh[4];
    }

    // ============ per-lane ldmatrix bases (relative to A buffer base) ============
    const int mat = lane >> 3, r8 = lane & 7;
    u32 aB[2];
#pragma unroll
    for (int mt = 0; mt < 2; mt++)
        aB[mt] = sb + SM_A0 + (u32)(16 * mt + ((mat & 1) << 3) + r8) * ASTRB
                 + (u32)((mat >> 1) << 3) * 2;
    const u32 bB4 = sb + SM_W + (u32)(8 * s + ((mat >> 1) << 3) + r8) * ASTRB
                    + (u32)((mat & 1) << 3) * 2;
    const u32 bB2 = sb + SM_W + (u32)(8 * (s + 2) + r8) * ASTRB
                    + (u32)((mat & 1) << 3) * 2;

    // ---- pre-load all weight fragments into registers ----
    u32 wb[KTILES][4];
    u32 w3[KTILES][2];
#pragma unroll
    for (int kt = 0; kt < KTILES; kt++) {
        ldsm_x4(wb[kt], bB4 + (u32)kt * 32);
        if (nt3) ldsm_x2(w3[kt], bB2 + (u32)kt * 32);
    }
    __syncthreads();   // x(0) stores + W reads complete

    // epilogue mapping + hoisted bias
    const int eg = lane >> 2, et2 = (lane & 3) * 2;
    float2 bias_r[3];
#pragma unroll
    for (int j = 0; j < 3; j++)
        bias_r[j] = *(const float2*)(smem + SM_BIAS + (8 * (s + j) + et2) * 4);

    float c[2][3][4];
#pragma unroll
    for (int mt = 0; mt < 2; mt++)
#pragma unroll
        for (int j = 0; j < 3; j++)
#pragma unroll
            for (int q = 0; q < 4; q++) c[mt][j][q] = 0.0f;

    // A fragment double buffer (registers)
    u32 fa[2][2][4];

#define LOADA(B, KO)                                 \
    do {                                             \
        ldsm_x4(fa[B][0], aB[0] + abuf + (KO));      \
        ldsm_x4(fa[B][1], aB[1] + abuf + (KO));      \
    } while (0)

#define MMAF(B, KT)                                                 \
    do {                                                            \
        mma_f16(c[0][0], fa[B][0], wb[KT][0], wb[KT][1]);           \
        mma_f16(c[1][0], fa[B][1], wb[KT][0], wb[KT][1]);           \
        mma_f16(c[0][1], fa[B][0], wb[KT][2], wb[KT][3]);           \
        mma_f16(c[1][1], fa[B][1], wb[KT][2], wb[KT][3]);           \
        if (nt3) {                                                  \
            mma_f16(c[0][2], fa[B][0], w3[KT][0], w3[KT][1]);       \
            mma_f16(c[1][2], fa[B][1], w3[KT][0], w3[KT][1]);       \
        }                                                           \
    } while (0)

    // ================= time loop (ONE barrier per step) =================
    for (int t = 0; t < T_SEQ; t++) {
        const u32 abuf = (u32)(t & 1) * ABUFSZ;        // read buffer
        const u32 wbuf = ABUFSZ - abuf;                // write buffer (t+1)

        // prefetch x(t+1)
        float4 v[4];
        const bool havex = (t + 1 < T_SEQ);
        if (havex) {
            const float* xp = Xrow + (long)(t + 1) * D_IN;
#pragma unroll
            for (int q = 0; q < 4; q++) v[q] = *(const float4*)(xp + 4 * q);
        }

        // ---- K loop: A double-buffered in regs, B from regs ----
        LOADA(0, 0u);
#pragma unroll
        for (int kt = 0; kt < KTILES; kt++) {
            const int cur = kt & 1;
            if (kt + 1 < KTILES) LOADA(cur ^ 1, (u32)(kt + 1) * 32);
            MMAF(cur, kt);
        }

        // ---- epilogue straight away: writes go to the OTHER buffer ----
        const bool last = (t == T_SEQ - 1);
#pragma unroll
        for (int mt = 0; mt < 2; mt++) {
            const int em = 16 * mt + eg;
#pragma unroll
            for (int j = 0; j < 3; j++) {
                if (j == 2 && !nt3) break;
                const int n = 8 * (s + j) + et2;
                float h00 = htanh(c[mt][j][0] + bias_r[j].x);
                float h01 = htanh(c[mt][j][1] + bias_r[j].y);
                float h10 = htanh(c[mt][j][2] + bias_r[j].x);
                float h11 = htanh(c[mt][j][3] + bias_r[j].y);
                u32 o0 = wbuf + (u32)em * ASTRB + (u32)(D_IN + n) * 2;
                u32 o1 = o0 + 8 * ASTRB;
                *(u32*)(smem + SM_A0 + o0) = cvt2h(h00, h01);
                *(u32*)(smem + SM_A0 + o1) = cvt2h(h10, h11);
                if (last) {
                    *(float2*)(smem + SM_HF + ((u32)em * NPAD + n) * 4)
                        = make_float2(h00, h01);
                    *(float2*)(smem + SM_HF + ((u32)(em + 8) * NPAD + n) * 4)
                        = make_float2(h10, h11);
                }
                c[mt][j][0] = 0.f; c[mt][j][1] = 0.f;
                c[mt][j][2] = 0.f; c[mt][j][3] = 0.f;
            }
        }

        // ---- store prefetched x(t+1) into the write buffer ----
        if (havex) {
            u32 hh[8];
#pragma unroll
            for (int q = 0; q < 4; q++) {
                hh[2*q]   = cvt2h(v[q].x, v[q].y);
                hh[2*q+1] = cvt2h(v[q].z, v[q].w);
            }
            *(uint4*)(smem + SM_A0 + wbuf + xdst)      = *(uint4*)&hh[0];
            *(uint4*)(smem + SM_A0 + wbuf + xdst + 16) = *(uint4*)&hh[4];
        }
        __syncthreads();   // write buffer complete -> readable next step
    }

    // ================= classifier head (fp32 h stash) =================
    for (int i = tid; i < M_BLK * O_OUT; i += NTHR) {
        const int b = i / O_OUT;
        const int o = i - b * O_OUT;
        float sacc = bo[o];
        const float* hrow = (const float*)(smem + SM_HF + (u32)b * NPAD * 4);
#pragma unroll 5
        for (int j = 0; j < H_HID; j++)
            sacc += hrow[j] * Wo[j * O_OUT + o];
        out[(ctaB0 + b) * O_OUT + o] = sacc;
    }
}

extern "C" void kernel_launch(void* const* d_in, const int* in_sizes, int n_in,
                              void* d_out, int out_size)
{
    const float* X  = (const float*)d_in[0];
    const float* Wc = (const float*)d_in[1];
    const float* bc = (const float*)d_in[2];
    const float* Wo = (const float*)d_in[3];
    const float* bo = (const float*)d_in[4];
    float* out = (float*)d_out;

    const int B = in_sizes[0] / (T_SEQ * D_IN);   // 4096

    cudaFuncSetAttribute(rnn_f16_db_kernel,
                         cudaFuncAttributeMaxDynamicSharedMemorySize, SMEM_BYTES);

    rnn_f16_db_kernel<<<B / M_BLK, NTHR, SMEM_BYTES>>>(X, Wc, bc, Wo, bo, out);
}